// round 17
// baseline (speedup 1.0000x reference)
#include <cuda_runtime.h>
#include <cuda_fp16.h>
#include <cstdint>

// ---------------------------------------------------------------------------
// Problem: x (8,2048,1024) -> 16384 tokens x 1024. Expert0 d=512, Expert1 d=256.
// Output: opt (16384*1024 fp32) + recon scalar.
// R17: dropout masks precomputed as bitmaps on a third stream (threefry is
// data-independent), overlapped with HBM-bound prep and tensor-bound GEMMs.
// EPI0 epilogues do word loads + bit tests instead of 32 threefry evals.
// Pure fp16 single-MMA GEMMs, BK=64, 3-stage cp.async, 2 CTAs/SM,
// expert chains on parallel streams (graph fork/join).
// ---------------------------------------------------------------------------
#define TOK   16384
#define HDIM  1024
#define NTOT  (TOK * HDIM)

// ---------------- static scratch (no allocs allowed) -----------------------
__device__ __half  g_hs16[NTOT];
__device__ __half  g_h16[2 * TOK * 512];
__device__ __half  g_t16[2 * TOK * 256];
__device__ __half  g_s16[2 * TOK * 512];
#define WTOT 2228224
__device__ __half  g_w16[WTOT];

// dropout mask bitmaps (1 bit per activation element)
#define MK_E0G1_OFF 0u
#define MK_E0S_OFF  262144u                 // TOK*512/32
#define MK_E1G1_OFF 393216u                 // +TOK*256/32
#define MK_E1S_OFF  524288u                 // +TOK*256/32
#define MK_TOTAL    589824u                 // +TOK*128/32
__device__ unsigned g_mask[MK_TOTAL];

// ---------------- threefry (exact JAX partitionable PRNG, verified R5) -----
__host__ __device__ __forceinline__ unsigned rotl32_(unsigned x, int r) {
    return (x << r) | (x >> (32 - r));
}
__host__ __device__ __forceinline__ void threefry2x32_(
    unsigned k0, unsigned k1, unsigned x0, unsigned x1,
    unsigned& o0, unsigned& o1)
{
    unsigned ks2 = k0 ^ k1 ^ 0x1BD11BDAu;
    unsigned ks[3] = {k0, k1, ks2};
    x0 += k0; x1 += k1;
    const int RA[4] = {13, 15, 26, 6};
    const int RB[4] = {17, 29, 16, 24};
#pragma unroll
    for (int r = 0; r < 5; ++r) {
        const int* R = (r & 1) ? RB : RA;
#pragma unroll
        for (int j = 0; j < 4; ++j) {
            x0 += x1; x1 = rotl32_(x1, R[j]); x1 ^= x0;
        }
        x0 += ks[(r + 1) % 3];
        x1 += ks[(r + 2) % 3] + (unsigned)(r + 1);
    }
    o0 = x0; o1 = x1;
}

// ---------------- PTX helpers (all plain sm_80-era ISA) --------------------
__device__ __forceinline__ uint32_t smem_u32(const void* p) {
    uint32_t a;
    asm("{ .reg .u64 t; cvta.to.shared.u64 t, %1; cvt.u32.u64 %0, t; }"
        : "=r"(a) : "l"(p));
    return a;
}
__device__ __forceinline__ void cp16(uint32_t s, const void* g) {
    asm volatile("cp.async.cg.shared.global [%0], [%1], 16;"
                 :: "r"(s), "l"(g));
}
__device__ __forceinline__ void cp_commit() {
    asm volatile("cp.async.commit_group;" ::: "memory");
}
template <int N>
__device__ __forceinline__ void cp_wait() {
    asm volatile("cp.async.wait_group %0;" :: "n"(N) : "memory");
}
__device__ __forceinline__ void ldmx4(uint32_t a, uint32_t& r0, uint32_t& r1,
                                      uint32_t& r2, uint32_t& r3) {
    asm volatile("ldmatrix.sync.aligned.m8n8.x4.shared.b16 {%0,%1,%2,%3}, [%4];"
                 : "=r"(r0), "=r"(r1), "=r"(r2), "=r"(r3) : "r"(a));
}
__device__ __forceinline__ void mma16816(float* c, const uint32_t* a,
                                         const uint32_t* b) {
    asm volatile(
        "mma.sync.aligned.m16n8k16.row.col.f32.f16.f16.f32 "
        "{%0,%1,%2,%3}, {%4,%5,%6,%7}, {%8,%9}, {%0,%1,%2,%3};"
        : "+f"(c[0]), "+f"(c[1]), "+f"(c[2]), "+f"(c[3])
        : "r"(a[0]), "r"(a[1]), "r"(a[2]), "r"(a[3]), "r"(b[0]), "r"(b[1]));
}

// ---------------------------------------------------------------------------
// Mask kernel: packs keep-bits (u < 0.8, exact JAX threefry bits) for the
// four dropout tensors. Sub segments pick the key for the selected branch
// (read from sub_choice on device); skipped entirely if sub_choice==2.
// ---------------------------------------------------------------------------
struct MaskArgs {
    unsigned off[4];
    unsigned end[4];
    unsigned key0[4], key1[4];   // primary key (kk1 for G1, kk2 for sub)
    unsigned alt0[4], alt1[4];   // kk3 for sub segments
    int      is_sub[4];
    int      expert[4];
};

__global__ void mask_kernel(MaskArgs a, const int* __restrict__ sub_choice,
                            unsigned* __restrict__ mask)
{
    unsigned w = blockIdx.x * 256 + threadIdx.x;
    if (w >= a.end[3]) return;
    int s = 0;
#pragma unroll
    for (int t = 0; t < 3; ++t)
        if (w >= a.end[t]) s = t + 1;
    unsigned k0 = a.key0[s], k1 = a.key1[s];
    if (a.is_sub[s]) {
        int sc = sub_choice[a.expert[s]];
        if (sc == 2) return;                 // branch unused
        if (sc == 1) { k0 = a.alt0[s]; k1 = a.alt1[s]; }
    }
    unsigned base = (w - a.off[s]) * 32u;
    unsigned m = 0;
#pragma unroll 4
    for (int b = 0; b < 32; ++b) {
        unsigned o0, o1;
        threefry2x32_(k0, k1, 0u, base + (unsigned)b, o0, o1);
        unsigned bits = o0 ^ o1;
        float u = __uint_as_float((bits >> 9) | 0x3f800000u) - 1.0f;
        m |= (u < 0.8f ? 1u : 0u) << b;
    }
    mask[w] = m;
}

// ---------------------------------------------------------------------------
// Prep: hs = x + 0.002*noise -> hs16; out passthrough ONLY where route==2.
// ---------------------------------------------------------------------------
__global__ void prep_kernel(const float* __restrict__ x,
                            const float* __restrict__ noise,
                            const int*   __restrict__ route,
                            float* __restrict__ out,
                            float* __restrict__ recon)
{
    unsigned i4 = blockIdx.x * blockDim.x + threadIdx.x;
    unsigned base = i4 * 4u;
    if (base < (unsigned)NTOT) {
        float4 xv = *(const float4*)(x + base);
        float4 nv = *(const float4*)(noise + base);
        float4 h;
        h.x = xv.x + 0.002f * nv.x;
        h.y = xv.y + 0.002f * nv.y;
        h.z = xv.z + 0.002f * nv.z;
        h.w = xv.w + 0.002f * nv.w;
        __half hv[4];
        hv[0] = __float2half(h.x); hv[1] = __float2half(h.y);
        hv[2] = __float2half(h.z); hv[3] = __float2half(h.w);
        *(uint2*)(g_hs16 + base) = *(uint2*)hv;
        int s = (int)((base >> 10) & 2047u);
        if (route[s] == 2) *(float4*)(out + base) = h;
    }
    if (i4 == 0) *recon = 0.0f;
}

// ---------------------------------------------------------------------------
// Fused weight prep: 12 matrices W[K,N] fp32 -> fp16 [N,K] (transposed)
// ---------------------------------------------------------------------------
struct WPrepArgs {
    const float* src[12];
    int K[12];
    int N[12];
    int pref[13];
};

__global__ void wprep_all(WPrepArgs a, __half* __restrict__ w16)
{
    int i = blockIdx.x * 256 + threadIdx.x;
    if (i >= a.pref[12]) return;
    int m = 0;
#pragma unroll
    for (int t = 0; t < 12; ++t)
        if (i >= a.pref[t + 1]) m = t + 1;
    int j = i - a.pref[m];
    int K = a.K[m], N = a.N[m];
    int n = j / K, k = j - n * K;
    w16[i] = __float2half(a.src[m][(size_t)k * N + n]);
}

// ---------------------------------------------------------------------------
// HMMA GEMM: tile 128x128, BK=64, 8 warps (4m x 2n), warp tile 32x64.
// Pure fp16 single-MMA, software-pipelined fragments, 3-stage cp.async.
// EPI 0: tanh -> masked dropout (bitmap) -> fp16
// EPI 1: tanh -> fp16
// EPI 2: route-select fp32 out + recon MSE (vs hs16)
// __launch_bounds__(256, 2): 2 CTAs/SM (smem 2x96KB).
// ---------------------------------------------------------------------------
#define TILE_B    16384
#define ST_A      0
#define ST_B      (TILE_B)
#define STAGE_B   (2 * TILE_B)
#define SMEM_BYTES (3 * STAGE_B)

__device__ __forceinline__ uint32_t sw_off(int r, int c) {
    return (uint32_t)(r * 128) + (uint32_t)((c ^ (r & 7)) << 4);
}

__device__ __forceinline__ void issue_stage(
    uint32_t sb, const __half* A, const __half* B,
    int brow, int bcol, int K, int k0, int tid)
{
#pragma unroll
    for (int it = 0; it < 4; ++it) {
        int idx = it * 256 + tid;
        int r = idx >> 3, c = idx & 7;
        uint32_t so = sw_off(r, c);
        size_t ga = (size_t)(brow + r) * K + k0 + c * 8;
        size_t gb = (size_t)(bcol + r) * K + k0 + c * 8;
        cp16(sb + ST_A + so, A + ga);
        cp16(sb + ST_B + so, B + gb);
    }
    cp_commit();
}

template <int EPI>
__global__ void __launch_bounds__(256, 2)
gemm_tc(const __half* __restrict__ A0, const __half* __restrict__ A1,
        const __half* __restrict__ B,
        const float* __restrict__ bias,
        __half* __restrict__ C,
        float* __restrict__ outC,
        int N, int K,
        const int* __restrict__ sub_choice, int expert, int branch_req,
        const unsigned* __restrict__ mask,
        const __half* __restrict__ hs16, const int* __restrict__ route,
        float* __restrict__ recon_out, float recon_scale)
{
    if (branch_req >= 0 && sub_choice[expert] != branch_req) return;
    const __half* A = A0;
    if (EPI == 2 && sub_choice[expert] < 2) A = A1;

    extern __shared__ char smem[];
    uint32_t sbase = smem_u32(smem);

    const int tid = threadIdx.x;
    const int wid = tid >> 5, lane = tid & 31;
    const int wm = wid >> 1, wn = wid & 1;
    const int brow = blockIdx.y * 128, bcol = blockIdx.x * 128;

    float acc[2][8][4];
#pragma unroll
    for (int mi = 0; mi < 2; ++mi)
#pragma unroll
        for (int nj = 0; nj < 8; ++nj)
#pragma unroll
            for (int c = 0; c < 4; ++c) acc[mi][nj][c] = 0.f;

    const int a_row = wm * 32 + (lane & 15);
    const int a_cb  = lane >> 4;
    const int b_row = wn * 64 + (lane & 7) + ((lane >> 4) << 3);
    const int b_cb  = (lane >> 3) & 1;

    uint32_t a_ro[2], b_ro[4];
    int a_swk[2], b_swk[4];
#pragma unroll
    for (int mi = 0; mi < 2; ++mi) {
        int r = a_row + mi * 16;
        a_ro[mi] = (uint32_t)(r * 128);
        a_swk[mi] = r & 7;
    }
#pragma unroll
    for (int g = 0; g < 4; ++g) {
        int r = b_row + g * 16;
        b_ro[g] = (uint32_t)(r * 128);
        b_swk[g] = r & 7;
    }

    const int nch = K >> 6;
    issue_stage(sbase,           A, B, brow, bcol, K, 0,  tid);
    issue_stage(sbase + STAGE_B, A, B, brow, bcol, K, 64, tid);

    int rs = 0, ws = 2;
    for (int kc = 0; kc < nch; ++kc) {
        if (kc + 1 < nch) cp_wait<1>(); else cp_wait<0>();
        __syncthreads();
        if (kc + 2 < nch)
            issue_stage(sbase + (uint32_t)ws * STAGE_B,
                        A, B, brow, bcol, K, (kc + 2) << 6, tid);

        uint32_t st = sbase + (uint32_t)rs * STAGE_B;

        uint32_t ah[2][2][4];
        uint32_t bh[2][4];
#pragma unroll
        for (int mi = 0; mi < 2; ++mi) {
            uint32_t ao = a_ro[mi] + (uint32_t)(((a_cb ^ a_swk[mi])) << 4);
            ldmx4(st + ST_A + ao,
                  ah[0][mi][0], ah[0][mi][1], ah[0][mi][2], ah[0][mi][3]);
        }
        {
            uint32_t bo = b_ro[0] + (uint32_t)(((b_cb ^ b_swk[0])) << 4);
            ldmx4(st + ST_B + bo, bh[0][0], bh[0][1], bh[0][2], bh[0][3]);
        }

#pragma unroll
        for (int s = 0; s < 16; ++s) {
            const int kk = s >> 2, g = s & 3;
            const int cur = s & 1, nxt = cur ^ 1;
            if (s < 15) {
                const int s2 = s + 1, kk2 = s2 >> 2, g2 = s2 & 3;
                if (g2 == 0) {
#pragma unroll
                    for (int mi = 0; mi < 2; ++mi) {
                        uint32_t ao = a_ro[mi] +
                            (uint32_t)((((kk2 * 2 + a_cb) ^ a_swk[mi])) << 4);
                        ldmx4(st + ST_A + ao,
                              ah[kk2 & 1][mi][0], ah[kk2 & 1][mi][1],
                              ah[kk2 & 1][mi][2], ah[kk2 & 1][mi][3]);
                    }
                }
                uint32_t bo = b_ro[g2] +
                    (uint32_t)((((kk2 * 2 + b_cb) ^ b_swk[g2])) << 4);
                ldmx4(st + ST_B + bo,
                      bh[nxt][0], bh[nxt][1], bh[nxt][2], bh[nxt][3]);
            }
#pragma unroll
            for (int p = 0; p < 2; ++p)
#pragma unroll
                for (int mi = 0; mi < 2; ++mi)
                    mma16816(acc[mi][g * 2 + p], ah[kk & 1][mi], &bh[cur][p * 2]);
        }
        rs = (rs == 2) ? 0 : rs + 1;
        ws = (ws == 2) ? 0 : ws + 1;
    }

    // ----------------- epilogue -----------------
    const int lane4 = lane >> 2;
    const int lanec = (lane & 3) * 2;
    float lsum = 0.f;

#pragma unroll
    for (int mi = 0; mi < 2; ++mi) {
        int r0g = brow + wm * 32 + mi * 16 + lane4;
        int r1g = r0g + 8;
        int rt0 = 0, rt1 = 0;
        unsigned m00 = 0, m01 = 0, m10 = 0, m11 = 0;
        if (EPI == 2) {
            rt0 = route[r0g & 2047];
            rt1 = route[r1g & 2047];
        }
        if (EPI == 0) {
            unsigned cb = (unsigned)(bcol + wn * 64);
            unsigned wb0 = ((unsigned)r0g * (unsigned)N + cb) >> 5;
            unsigned wb1 = ((unsigned)r1g * (unsigned)N + cb) >> 5;
            m00 = mask[wb0]; m01 = mask[wb0 + 1];
            m10 = mask[wb1]; m11 = mask[wb1 + 1];
        }
#pragma unroll
        for (int nj = 0; nj < 8; ++nj) {
            int col = bcol + wn * 64 + nj * 8 + lanec;
            float b0 = bias[col], b1 = bias[col + 1];
            float v00 = acc[mi][nj][0] + b0, v01 = acc[mi][nj][1] + b1;
            float v10 = acc[mi][nj][2] + b0, v11 = acc[mi][nj][3] + b1;
            unsigned i0 = (unsigned)r0g * (unsigned)N + (unsigned)col;
            unsigned i1 = (unsigned)r1g * (unsigned)N + (unsigned)col;

            if (EPI == 0 || EPI == 1) {
                v00 = tanhf(v00); v01 = tanhf(v01);
                v10 = tanhf(v10); v11 = tanhf(v11);
                if (EPI == 0) {
                    int j = nj * 8 + lanec;          // even, < 63
                    unsigned s0 = (j < 32) ? m00 : m01;
                    unsigned s1 = (j < 32) ? m10 : m11;
                    int sh = j & 31;
                    v00 = ((s0 >> sh) & 1u) ? v00 * 1.25f : 0.f;
                    v01 = ((s0 >> (sh + 1)) & 1u) ? v01 * 1.25f : 0.f;
                    v10 = ((s1 >> sh) & 1u) ? v10 * 1.25f : 0.f;
                    v11 = ((s1 >> (sh + 1)) & 1u) ? v11 * 1.25f : 0.f;
                }
                __half2 p0, p1;
                p0.x = __float2half(v00); p0.y = __float2half(v01);
                p1.x = __float2half(v10); p1.y = __float2half(v11);
                *(__half2*)(C + i0) = p0;
                *(__half2*)(C + i1) = p1;
            } else {
                __half2 h0 = *(const __half2*)(hs16 + i0);
                __half2 h1 = *(const __half2*)(hs16 + i1);
                float d;
                d = __half2float(h0.x) - v00; lsum += d * d;
                d = __half2float(h0.y) - v01; lsum += d * d;
                d = __half2float(h1.x) - v10; lsum += d * d;
                d = __half2float(h1.y) - v11; lsum += d * d;
                if (rt0 == expert) {
                    outC[i0] = v00; outC[i0 + 1] = v01;
                }
                if (rt1 == expert) {
                    outC[i1] = v10; outC[i1 + 1] = v11;
                }
            }
        }
    }

    if (EPI == 2) {
#pragma unroll
        for (int s = 16; s > 0; s >>= 1)
            lsum += __shfl_xor_sync(0xFFFFFFFFu, lsum, s);
        if (lane == 0) atomicAdd(recon_out, lsum * recon_scale);
    }
}

// ---------------------------------------------------------------------------
// Host side: masks on s2 at t0; prep+wprep on default; FORK -> expert0 on
// default, expert1 on s1 (both wait mask event) -> JOIN.
// ---------------------------------------------------------------------------
extern "C" void kernel_launch(void* const* d_in, const int* in_sizes, int n_in,
                              void* d_out, int out_size)
{
    const float* x          = (const float*)d_in[0];
    const float* noise      = (const float*)d_in[1];
    const int*   route      = (const int*)  d_in[2];
    const int*   sub_choice = (const int*)  d_in[3];

    float* out   = (float*)d_out;
    float* recon = out + (out_size - 1);

    __half *p_hs16, *p_h16, *p_t16, *p_s16, *p_w16;
    unsigned* p_mask;
    cudaGetSymbolAddress((void**)&p_hs16, g_hs16);
    cudaGetSymbolAddress((void**)&p_h16,  g_h16);
    cudaGetSymbolAddress((void**)&p_t16,  g_t16);
    cudaGetSymbolAddress((void**)&p_s16,  g_s16);
    cudaGetSymbolAddress((void**)&p_w16,  g_w16);
    cudaGetSymbolAddress((void**)&p_mask, g_mask);

    static cudaStream_t s1 = nullptr, s2 = nullptr;
    static cudaEvent_t ev_start = nullptr, ev_mask = nullptr,
                       ev_fork = nullptr, ev_join = nullptr;
    if (s1 == nullptr) {
        cudaStreamCreateWithFlags(&s1, cudaStreamNonBlocking);
        cudaStreamCreateWithFlags(&s2, cudaStreamNonBlocking);
        cudaEventCreateWithFlags(&ev_start, cudaEventDisableTiming);
        cudaEventCreateWithFlags(&ev_mask, cudaEventDisableTiming);
        cudaEventCreateWithFlags(&ev_fork, cudaEventDisableTiming);
        cudaEventCreateWithFlags(&ev_join, cudaEventDisableTiming);
        cudaFuncSetAttribute(gemm_tc<0>, cudaFuncAttributeMaxDynamicSharedMemorySize, SMEM_BYTES);
        cudaFuncSetAttribute(gemm_tc<1>, cudaFuncAttributeMaxDynamicSharedMemorySize, SMEM_BYTES);
        cudaFuncSetAttribute(gemm_tc<2>, cudaFuncAttributeMaxDynamicSharedMemorySize, SMEM_BYTES);
    }

    // --- exact JAX partitionable key derivation (verified R5) ---
    unsigned ek[2][2];
    threefry2x32_(0u, 42u, 0u, 0u, ek[0][0], ek[0][1]);
    threefry2x32_(0u, 42u, 0u, 1u, ek[1][0], ek[1][1]);
    unsigned kk1[2][2], kk2[2][2], kk3[2][2];
    for (int e = 0; e < 2; ++e) {
        threefry2x32_(ek[e][0], ek[e][1], 0u, 0u, kk1[e][0], kk1[e][1]);
        threefry2x32_(ek[e][0], ek[e][1], 0u, 1u, kk2[e][0], kk2[e][1]);
        threefry2x32_(ek[e][0], ek[e][1], 0u, 2u, kk3[e][0], kk3[e][1]);
    }

    // --- mask bitmaps on s2, overlapped with prep/wprep/GEMM1 mainloops ---
    cudaEventRecord(ev_start, 0);
    cudaStreamWaitEvent(s2, ev_start, 0);
    {
        MaskArgs ma;
        unsigned offs[4] = {MK_E0G1_OFF, MK_E0S_OFF, MK_E1G1_OFF, MK_E1S_OFF};
        unsigned ends[4] = {MK_E0S_OFF, MK_E1G1_OFF, MK_E1S_OFF, MK_TOTAL};
        for (int s = 0; s < 4; ++s) { ma.off[s] = offs[s]; ma.end[s] = ends[s]; }
        ma.key0[0] = kk1[0][0]; ma.key1[0] = kk1[0][1];
        ma.key0[1] = kk2[0][0]; ma.key1[1] = kk2[0][1];
        ma.alt0[1] = kk3[0][0]; ma.alt1[1] = kk3[0][1];
        ma.key0[2] = kk1[1][0]; ma.key1[2] = kk1[1][1];
        ma.key0[3] = kk2[1][0]; ma.key1[3] = kk2[1][1];
        ma.alt0[3] = kk3[1][0]; ma.alt1[3] = kk3[1][1];
        ma.alt0[0] = ma.alt1[0] = ma.alt0[2] = ma.alt1[2] = 0;
        ma.is_sub[0] = 0; ma.is_sub[1] = 1; ma.is_sub[2] = 0; ma.is_sub[3] = 1;
        ma.expert[0] = 0; ma.expert[1] = 0; ma.expert[2] = 1; ma.expert[3] = 1;
        mask_kernel<<<(MK_TOTAL + 255) / 256, 256, 0, s2>>>(ma, sub_choice, p_mask);
    }
    cudaEventRecord(ev_mask, s2);

    prep_kernel<<<NTOT / 4 / 256, 256>>>(x, noise, route, out, recon);

    // --- fused weight prep: 12 matrices, one launch ---
    long woff[2][6];
    WPrepArgs wa;
    {
        int off = 0, m = 0;
        for (int e = 0; e < 2; ++e) {
            int base = 4 + e * 12;
            int d = (e == 0) ? 512 : 256, dh = d / 2;
            const float* srcs[6] = {
                (const float*)d_in[base + 0],
                (const float*)d_in[base + 2],
                (const float*)d_in[base + 4],
                (const float*)d_in[base + 6],
                (const float*)d_in[base + 8],
                (const float*)d_in[base + 10],
            };
            int Ks[6] = {HDIM, d, dh, d, dh, d};
            int Ns[6] = {d, dh, d, dh, d, HDIM};
            for (int wi = 0; wi < 6; ++wi, ++m) {
                woff[e][wi] = off;
                wa.src[m] = srcs[wi];
                wa.K[m] = Ks[wi];
                wa.N[m] = Ns[wi];
                wa.pref[m] = off;
                off += Ks[wi] * Ns[wi];
            }
        }
        wa.pref[12] = off;
        wprep_all<<<(off + 255) / 256, 256>>>(wa, p_w16);
    }

    // FORK (expert1 on s1); both streams wait for masks
    cudaEventRecord(ev_fork, 0);
    cudaStreamWaitEvent(s1, ev_fork, 0);
    cudaStreamWaitEvent(0, ev_mask, 0);
    cudaStreamWaitEvent(s1, ev_mask, 0);

    const float recon_scale = 1.0f / (2.0f * (float)NTOT);
    const unsigned* mk_g1[2] = {p_mask + MK_E0G1_OFF, p_mask + MK_E1G1_OFF};
    const unsigned* mk_s[2]  = {p_mask + MK_E0S_OFF,  p_mask + MK_E1S_OFF};

    for (int e = 0; e < 2; ++e) {
        int base = 4 + e * 12;
        const float* db   = (const float*)d_in[base + 1];
        const float* s0db = (const float*)d_in[base + 3];
        const float* s0ub = (const float*)d_in[base + 5];
        const float* s1db = (const float*)d_in[base + 7];
        const float* s1ub = (const float*)d_in[base + 9];
        const float* ub   = (const float*)d_in[base + 11];
        int d = (e == 0) ? 512 : 256, dh = d / 2;
        cudaStream_t st = (e == 0) ? (cudaStream_t)0 : s1;

        __half* h16  = p_h16 + (size_t)e * TOK * 512;
        __half* t16  = p_t16 + (size_t)e * TOK * 256;
        __half* sv16 = p_s16 + (size_t)e * TOK * 512;

        // GEMM1: hs @ dw -> tanh -> masked dropout -> h
        gemm_tc<0><<<dim3(d / 128, TOK / 128), 256, SMEM_BYTES, st>>>(
            p_hs16, nullptr, p_w16 + woff[e][0], db,
            h16, nullptr,
            d, HDIM, sub_choice, e, -1, mk_g1[e],
            nullptr, nullptr, nullptr, 0.f);

        // s0 branch
        gemm_tc<0><<<dim3(dh / 128, TOK / 128), 256, SMEM_BYTES, st>>>(
            h16, nullptr, p_w16 + woff[e][1], s0db,
            t16, nullptr,
            dh, d, sub_choice, e, 0, mk_s[e],
            nullptr, nullptr, nullptr, 0.f);
        gemm_tc<1><<<dim3(d / 128, TOK / 128), 256, SMEM_BYTES, st>>>(
            t16, nullptr, p_w16 + woff[e][2], s0ub,
            sv16, nullptr,
            d, dh, sub_choice, e, 0, nullptr,
            nullptr, nullptr, nullptr, 0.f);

        // s1 branch
        gemm_tc<0><<<dim3(dh / 128, TOK / 128), 256, SMEM_BYTES, st>>>(
            h16, nullptr, p_w16 + woff[e][3], s1db,
            t16, nullptr,
            dh, d, sub_choice, e, 1, mk_s[e],
            nullptr, nullptr, nullptr, 0.f);
        gemm_tc<1><<<dim3(d / 128, TOK / 128), 256, SMEM_BYTES, st>>>(
            t16, nullptr, p_w16 + woff[e][4], s1ub,
            sv16, nullptr,
            d, dh, sub_choice, e, 1, nullptr,
            nullptr, nullptr, nullptr, 0.f);

        // GEMM3: (choice<2 ? s : h) @ uw -> route-select out + recon
        gemm_tc<2><<<dim3(HDIM / 128, TOK / 128), 256, SMEM_BYTES, st>>>(
            h16, sv16, p_w16 + woff[e][5], ub,
            nullptr, out,
            HDIM, d, sub_choice, e, -1, nullptr,
            p_hs16, route, recon, recon_scale);
    }

    // JOIN
    cudaEventRecord(ev_join, s1);
    cudaStreamWaitEvent(0, ev_join, 0);
}